// round 1
// baseline (speedup 1.0000x reference)
#include <cuda_runtime.h>
#include <math.h>

#define B_ 2
#define L_ 1024
#define D_ 768
#define H_ 12
#define HD_ 64
#define FF_ 3072
#define V_ 32000
#define NL_ 2
#define TOK_BOS 1
#define TOK_SEP 2
#define WIN_ 512
#define EPS_ 1e-5f
#define M_ (B_ * L_) /* 2048 rows */

// ---------------- scratch (static device globals; no allocation) ------------
__device__ float g_x[M_ * D_];
__device__ float g_h[M_ * D_];
__device__ float g_qkv[M_ * 3 * D_];
__device__ float g_y[M_ * D_];
__device__ float g_ff[M_ * FF_];
__device__ float g_sc[(size_t)B_ * H_ * L_ * L_];   // 100.7 MB
__device__ int   g_seg[B_ * L_];
__device__ int   g_gkey[B_ * L_];
__device__ int   g_valid[B_ * L_];

// ---------------- embedding -------------------------------------------------
__global__ void k_embed(const int* __restrict__ tokens, const int* __restrict__ types,
                        const float* __restrict__ tok_emb, const float* __restrict__ type_emb,
                        const float* __restrict__ pos_emb) {
    int idx = blockIdx.x * blockDim.x + threadIdx.x;
    if (idx >= M_ * D_) return;
    int d = idx % D_;
    int bl = idx / D_;
    int l = bl % L_;
    g_x[idx] = tok_emb[(size_t)tokens[bl] * D_ + d]
             + type_emb[(size_t)types[bl] * D_ + d]
             + pos_emb[(size_t)l * D_ + d];
}

// ---------------- mask metadata (seg cumsum, global keys, validity) ---------
__global__ void k_maskprep(const int* __restrict__ tokens, const int* __restrict__ attn_mask) {
    int b = threadIdx.x;
    if (b >= B_) return;
    int seg = 0;
    for (int l = 0; l < L_; l++) {
        int i = b * L_ + l;
        int va = attn_mask[i] != 0;
        int tok = tokens[i];
        int is_sep = (tok == TOK_SEP) && va;
        seg += is_sep;
        g_seg[i] = seg;
        g_gkey[i] = (((tok == TOK_BOS) && va) || is_sep) ? 1 : 0;
        g_valid[i] = va;
    }
}

// ---------------- layernorm (one block per row, 256 thr, D=768) -------------
__global__ __launch_bounds__(256)
void k_ln(const float* __restrict__ x, const float* __restrict__ sc,
          const float* __restrict__ bi, float* __restrict__ out) {
    int row = blockIdx.x;
    const float* xr = x + (size_t)row * D_;
    int t = threadIdx.x;
    float v0 = xr[t], v1 = xr[t + 256], v2 = xr[t + 512];
    float s = v0 + v1 + v2;
    float ss = v0 * v0 + v1 * v1 + v2 * v2;
    __shared__ float rs[8], rq[8];
#pragma unroll
    for (int o = 16; o > 0; o >>= 1) {
        s  += __shfl_xor_sync(0xffffffffu, s, o);
        ss += __shfl_xor_sync(0xffffffffu, ss, o);
    }
    if ((t & 31) == 0) { rs[t >> 5] = s; rq[t >> 5] = ss; }
    __syncthreads();
    if (t < 32) {
        float a = (t < 8) ? rs[t] : 0.f;
        float q = (t < 8) ? rq[t] : 0.f;
#pragma unroll
        for (int o = 4; o > 0; o >>= 1) {
            a += __shfl_xor_sync(0xffffffffu, a, o);
            q += __shfl_xor_sync(0xffffffffu, q, o);
        }
        if (t == 0) { rs[0] = a; rq[0] = q; }
    }
    __syncthreads();
    float mean = rs[0] * (1.0f / D_);
    float var  = rq[0] * (1.0f / D_) - mean * mean;
    float inv = rsqrtf(var + EPS_);
    float* orow = out + (size_t)row * D_;
    orow[t]       = (v0 - mean) * inv * sc[t]       + bi[t];
    orow[t + 256] = (v1 - mean) * inv * sc[t + 256] + bi[t + 256];
    orow[t + 512] = (v2 - mean) * inv * sc[t + 512] + bi[t + 512];
}

// ---------------- SGEMM NT: C[M,N] = A[M,K] @ Bw[N,K]^T (+bias/+resid/gelu) --
// 128x128 tile, BK=8, 256 threads, 8x8 micro-tile. M%128==0, N%128==0, K%8==0.
__global__ __launch_bounds__(256, 2)
void k_sgemm_nt(const float* __restrict__ A, const float* __restrict__ Bw,
                float* __restrict__ C, int M, int N, int K,
                const float* __restrict__ bias, const float* __restrict__ resid,
                int dogelu) {
    __shared__ float As[8][128];
    __shared__ float Bs[8][128];
    const int bm = blockIdx.y * 128;
    const int bn = blockIdx.x * 128;
    const int tid = threadIdx.x;
    const int lr = tid >> 1;
    const int lc = (tid & 1) * 4;
    const float* Ag = A  + (size_t)(bm + lr) * K + lc;
    const float* Bg = Bw + (size_t)(bn + lr) * K + lc;
    const int tm = (tid >> 4) * 8;
    const int tn = (tid & 15) * 8;
    float acc[8][8];
#pragma unroll
    for (int i = 0; i < 8; i++)
#pragma unroll
        for (int j = 0; j < 8; j++) acc[i][j] = 0.f;

    for (int k0 = 0; k0 < K; k0 += 8) {
        float4 a4 = *(const float4*)(Ag + k0);
        float4 b4 = *(const float4*)(Bg + k0);
        As[lc + 0][lr] = a4.x; As[lc + 1][lr] = a4.y; As[lc + 2][lr] = a4.z; As[lc + 3][lr] = a4.w;
        Bs[lc + 0][lr] = b4.x; Bs[lc + 1][lr] = b4.y; Bs[lc + 2][lr] = b4.z; Bs[lc + 3][lr] = b4.w;
        __syncthreads();
#pragma unroll
        for (int kk = 0; kk < 8; kk++) {
            float4 a0 = *(const float4*)&As[kk][tm];
            float4 a1 = *(const float4*)&As[kk][tm + 4];
            float4 b0 = *(const float4*)&Bs[kk][tn];
            float4 b1 = *(const float4*)&Bs[kk][tn + 4];
            float a[8] = {a0.x, a0.y, a0.z, a0.w, a1.x, a1.y, a1.z, a1.w};
            float b[8] = {b0.x, b0.y, b0.z, b0.w, b1.x, b1.y, b1.z, b1.w};
#pragma unroll
            for (int i = 0; i < 8; i++)
#pragma unroll
                for (int j = 0; j < 8; j++) acc[i][j] += a[i] * b[j];
        }
        __syncthreads();
    }
#pragma unroll
    for (int i = 0; i < 8; i++) {
        int m = bm + tm + i;
#pragma unroll
        for (int j = 0; j < 8; j++) {
            int n = bn + tn + j;
            float v = acc[i][j];
            if (bias)  v += bias[n];
            if (resid) v += resid[(size_t)m * N + n];
            if (dogelu) v = 0.5f * v * (1.0f + erff(v * 0.70710678118654752f));
            C[(size_t)m * N + n] = v;
        }
    }
}

// ---------------- attention scores: S = Q K^T * scale + box-mask ------------
__global__ __launch_bounds__(256)
void k_scores(const float* __restrict__ qkv) {
    const int bh = blockIdx.z;
    const int b = bh / H_, h = bh % H_;
    const int i0 = blockIdx.y * 64, j0 = blockIdx.x * 64;
    const int t = threadIdx.x;
    const int tm = (t >> 4) * 4, tn = (t & 15) * 4;
    const size_t sbase = ((size_t)bh * L_ + i0) * L_ + j0;

    if (j0 > i0 + 63) { // fully above the diagonal: all masked
#pragma unroll
        for (int i = 0; i < 4; i++)
#pragma unroll
            for (int j = 0; j < 4; j++)
                g_sc[sbase + (size_t)(tm + i) * L_ + tn + j] = -1e30f;
        return;
    }

    __shared__ float Qs[64][65];
    __shared__ float Ks[64][65];
    const float* qb = qkv + (size_t)(b * L_ + i0) * (3 * D_) + h * HD_;
    const float* kb = qkv + (size_t)(b * L_ + j0) * (3 * D_) + D_ + h * HD_;
    for (int idx = t; idx < 64 * 64; idx += 256) {
        int r = idx >> 6, c = idx & 63;
        Qs[r][c] = qb[(size_t)r * (3 * D_) + c];
        Ks[r][c] = kb[(size_t)r * (3 * D_) + c];
    }
    __syncthreads();

    float acc[4][4] = {};
#pragma unroll 8
    for (int d = 0; d < 64; d++) {
        float q[4], k[4];
#pragma unroll
        for (int i = 0; i < 4; i++) { q[i] = Qs[tm + i][d]; k[i] = Ks[tn + i][d]; }
#pragma unroll
        for (int i = 0; i < 4; i++)
#pragma unroll
            for (int j = 0; j < 4; j++) acc[i][j] += q[i] * k[j];
    }

    const int* segb = g_seg + b * L_;
    const int* gkb  = g_gkey + b * L_;
    const int* vab  = g_valid + b * L_;
#pragma unroll
    for (int i = 0; i < 4; i++) {
        int gi = i0 + tm + i;
        int si = segb[gi];
#pragma unroll
        for (int j = 0; j < 4; j++) {
            int gj = j0 + tn + j;
            float v = acc[i][j] * 0.125f; // 1/sqrt(64)
            bool allowed = (gj <= gi) && vab[gj] &&
                           (segb[gj] == si || gkb[gj] || (gi - gj) <= WIN_);
            g_sc[sbase + (size_t)(tm + i) * L_ + tn + j] = allowed ? v : -1e30f;
        }
    }
}

// ---------------- row softmax over L=1024 -----------------------------------
__global__ __launch_bounds__(256)
void k_softmax() {
    size_t row = blockIdx.x;
    float* p = g_sc + row * L_;
    int t = threadIdx.x;
    float v[4];
    float mx = -1e30f;
#pragma unroll
    for (int i = 0; i < 4; i++) { v[i] = p[i * 256 + t]; mx = fmaxf(mx, v[i]); }
    __shared__ float rmax[8], rsum[8];
#pragma unroll
    for (int o = 16; o > 0; o >>= 1) mx = fmaxf(mx, __shfl_xor_sync(0xffffffffu, mx, o));
    if ((t & 31) == 0) rmax[t >> 5] = mx;
    __syncthreads();
    if (t < 32) {
        float m = (t < 8) ? rmax[t] : -1e30f;
#pragma unroll
        for (int o = 4; o > 0; o >>= 1) m = fmaxf(m, __shfl_xor_sync(0xffffffffu, m, o));
        if (t == 0) rmax[0] = m;
    }
    __syncthreads();
    float bm = rmax[0];
    float s = 0.f;
#pragma unroll
    for (int i = 0; i < 4; i++) { v[i] = __expf(v[i] - bm); s += v[i]; }
#pragma unroll
    for (int o = 16; o > 0; o >>= 1) s += __shfl_xor_sync(0xffffffffu, s, o);
    if ((t & 31) == 0) rsum[t >> 5] = s;
    __syncthreads();
    if (t < 32) {
        float a = (t < 8) ? rsum[t] : 0.f;
#pragma unroll
        for (int o = 4; o > 0; o >>= 1) a += __shfl_xor_sync(0xffffffffu, a, o);
        if (t == 0) rsum[0] = a;
    }
    __syncthreads();
    float inv = 1.0f / rsum[0];
#pragma unroll
    for (int i = 0; i < 4; i++) p[i * 256 + t] = v[i] * inv;
}

// ---------------- y = P @ V (per (b,h), 64-query tiles, causal skip) --------
__global__ __launch_bounds__(256)
void k_av(const float* __restrict__ qkv) {
    const int bh = blockIdx.y;
    const int b = bh / H_, h = bh % H_;
    const int i0 = blockIdx.x * 64;
    const int t = threadIdx.x;
    const int tm = (t >> 4) * 4, tn = (t & 15) * 4;
    __shared__ float Ps[64][65];
    __shared__ float Vs[64][65];
    float acc[4][4] = {};
    const float* vb = qkv + (size_t)b * L_ * 3 * D_ + 2 * D_ + h * HD_;
    for (int j0 = 0; j0 <= i0 + 63; j0 += 64) {
        for (int idx = t; idx < 64 * 64; idx += 256) {
            int r = idx >> 6, c = idx & 63;
            Ps[r][c] = g_sc[((size_t)bh * L_ + i0 + r) * L_ + j0 + c];
            Vs[r][c] = vb[(size_t)(j0 + r) * 3 * D_ + c];
        }
        __syncthreads();
#pragma unroll 4
        for (int jj = 0; jj < 64; jj++) {
            float pr[4], vv[4];
#pragma unroll
            for (int i = 0; i < 4; i++) { pr[i] = Ps[tm + i][jj]; vv[i] = Vs[jj][tn + i]; }
#pragma unroll
            for (int i = 0; i < 4; i++)
#pragma unroll
                for (int j = 0; j < 4; j++) acc[i][j] += pr[i] * vv[j];
        }
        __syncthreads();
    }
    float* yb = g_y + (size_t)(b * L_ + i0) * D_ + h * HD_;
#pragma unroll
    for (int i = 0; i < 4; i++)
#pragma unroll
        for (int j = 0; j < 4; j++)
            yb[(size_t)(tm + i) * D_ + tn + j] = acc[i][j];
}

// ---------------- host side --------------------------------------------------
static void gemm(const float* A, const float* Bw, float* C, int M, int N, int K,
                 const float* bias, const float* resid, bool gelu_flag) {
    dim3 grid(N / 128, M / 128);
    k_sgemm_nt<<<grid, 256>>>(A, Bw, C, M, N, K, bias, resid, gelu_flag ? 1 : 0);
}

extern "C" void kernel_launch(void* const* d_in, const int* in_sizes, int n_in,
                              void* d_out, int out_size) {
    const int*   tokens    = (const int*)d_in[0];
    const int*   types     = (const int*)d_in[1];
    const int*   attn_mask = (const int*)d_in[2];
    const float* tok_emb   = (const float*)d_in[3];
    const float* type_emb  = (const float*)d_in[4];
    const float* pos_emb   = (const float*)d_in[5];
    const float* qkv_w     = (const float*)d_in[6];
    const float* out_w     = (const float*)d_in[7];
    const float* ln1_s     = (const float*)d_in[8];
    const float* ln1_b     = (const float*)d_in[9];
    const float* ln2_s     = (const float*)d_in[10];
    const float* ln2_b     = (const float*)d_in[11];
    const float* ff_w1     = (const float*)d_in[12];
    const float* ff_b1     = (const float*)d_in[13];
    const float* ff_w2     = (const float*)d_in[14];
    const float* ff_b2     = (const float*)d_in[15];
    const float* lnf_s     = (const float*)d_in[16];
    const float* lnf_b     = (const float*)d_in[17];
    const float* head_w    = (const float*)d_in[18];
    float* out = (float*)d_out;

    float *x, *h, *qkv, *y, *ff;
    cudaGetSymbolAddress((void**)&x, g_x);
    cudaGetSymbolAddress((void**)&h, g_h);
    cudaGetSymbolAddress((void**)&qkv, g_qkv);
    cudaGetSymbolAddress((void**)&y, g_y);
    cudaGetSymbolAddress((void**)&ff, g_ff);

    k_embed<<<(M_ * D_ + 255) / 256, 256>>>(tokens, types, tok_emb, type_emb, pos_emb);
    k_maskprep<<<1, 32>>>(tokens, attn_mask);

    for (int l = 0; l < NL_; l++) {
        k_ln<<<M_, 256>>>(x, ln1_s + l * D_, ln1_b + l * D_, h);
        gemm(h, qkv_w + (size_t)l * 3 * D_ * D_, qkv, M_, 3 * D_, D_, nullptr, nullptr, false);
        k_scores<<<dim3(L_ / 64, L_ / 64, B_ * H_), 256>>>(qkv);
        k_softmax<<<B_ * H_ * L_, 256>>>();
        k_av<<<dim3(L_ / 64, B_ * H_), 256>>>(qkv);
        gemm(y, out_w + (size_t)l * D_ * D_, x, M_, D_, D_, nullptr, x, false);
        k_ln<<<M_, 256>>>(x, ln2_s + l * D_, ln2_b + l * D_, h);
        gemm(h, ff_w1 + (size_t)l * FF_ * D_, ff, M_, FF_, D_, ff_b1 + l * FF_, nullptr, true);
        gemm(ff, ff_w2 + (size_t)l * D_ * FF_, x, M_, D_, FF_, ff_b2 + l * D_, x, false);
    }
    k_ln<<<M_, 256>>>(x, lnf_s, lnf_b, h);
    gemm(h, head_w, out, M_, V_, D_, nullptr, nullptr, false);
}

// round 2
// speedup vs baseline: 2.1657x; 2.1657x over previous
#include <cuda_runtime.h>
#include <math.h>

#define B_ 2
#define L_ 1024
#define D_ 768
#define H_ 12
#define HD_ 64
#define FF_ 3072
#define V_ 32000
#define NL_ 2
#define TOK_BOS 1
#define TOK_SEP 2
#define WIN_ 512
#define EPS_ 1e-5f
#define M_ (B_ * L_) /* 2048 rows */

// ---------------- scratch (static device globals; no allocation) ------------
__device__ float g_x[M_ * D_];
__device__ float g_h[M_ * D_];
__device__ float g_qkv[M_ * 3 * D_];
__device__ float g_y[M_ * D_];
__device__ float g_ff[M_ * FF_];
__device__ float g_sc[(size_t)B_ * H_ * L_ * L_];   // 100.7 MB
__device__ int   g_seg[B_ * L_];
__device__ int   g_gkey[B_ * L_];
__device__ int   g_valid[B_ * L_];

// ---------------- embedding -------------------------------------------------
__global__ void k_embed(const int* __restrict__ tokens, const int* __restrict__ types,
                        const float* __restrict__ tok_emb, const float* __restrict__ type_emb,
                        const float* __restrict__ pos_emb) {
    int idx = blockIdx.x * blockDim.x + threadIdx.x;
    if (idx >= M_ * D_) return;
    int d = idx % D_;
    int bl = idx / D_;
    int l = bl % L_;
    g_x[idx] = tok_emb[(size_t)tokens[bl] * D_ + d]
             + type_emb[(size_t)types[bl] * D_ + d]
             + pos_emb[(size_t)l * D_ + d];
}

// ---------------- mask metadata ----------------------------------------------
__global__ void k_maskprep(const int* __restrict__ tokens, const int* __restrict__ attn_mask) {
    int b = threadIdx.x;
    if (b >= B_) return;
    int seg = 0;
    for (int l = 0; l < L_; l++) {
        int i = b * L_ + l;
        int va = attn_mask[i] != 0;
        int tok = tokens[i];
        int is_sep = (tok == TOK_SEP) && va;
        seg += is_sep;
        g_seg[i] = seg;
        g_gkey[i] = (((tok == TOK_BOS) && va) || is_sep) ? 1 : 0;
        g_valid[i] = va;
    }
}

// ---------------- layernorm --------------------------------------------------
__global__ __launch_bounds__(256)
void k_ln(const float* __restrict__ x, const float* __restrict__ sc,
          const float* __restrict__ bi, float* __restrict__ out) {
    int row = blockIdx.x;
    const float* xr = x + (size_t)row * D_;
    int t = threadIdx.x;
    float v0 = xr[t], v1 = xr[t + 256], v2 = xr[t + 512];
    float s = v0 + v1 + v2;
    float ss = v0 * v0 + v1 * v1 + v2 * v2;
    __shared__ float rs[8], rq[8];
#pragma unroll
    for (int o = 16; o > 0; o >>= 1) {
        s  += __shfl_xor_sync(0xffffffffu, s, o);
        ss += __shfl_xor_sync(0xffffffffu, ss, o);
    }
    if ((t & 31) == 0) { rs[t >> 5] = s; rq[t >> 5] = ss; }
    __syncthreads();
    if (t < 32) {
        float a = (t < 8) ? rs[t] : 0.f;
        float q = (t < 8) ? rq[t] : 0.f;
#pragma unroll
        for (int o = 4; o > 0; o >>= 1) {
            a += __shfl_xor_sync(0xffffffffu, a, o);
            q += __shfl_xor_sync(0xffffffffu, q, o);
        }
        if (t == 0) { rs[0] = a; rq[0] = q; }
    }
    __syncthreads();
    float mean = rs[0] * (1.0f / D_);
    float var  = rq[0] * (1.0f / D_) - mean * mean;
    float inv = rsqrtf(var + EPS_);
    float* orow = out + (size_t)row * D_;
    orow[t]       = (v0 - mean) * inv * sc[t]       + bi[t];
    orow[t + 256] = (v1 - mean) * inv * sc[t + 256] + bi[t + 256];
    orow[t + 512] = (v2 - mean) * inv * sc[t + 512] + bi[t + 512];
}

// ---------------- TF32 tensor-core GEMM NT -----------------------------------
// C[M,N] = A[M,K] @ Bw[N,K]^T (+bias/+resid/gelu)
// 128x128 block tile, BK=16, 256 threads = 8 warps (2 M x 4 N), warp tile 64x32.
// mma.sync.m16n8k8 tf32, fp32 accumulate, double-buffered smem.
__device__ __forceinline__ unsigned f2tf(float x) {
    unsigned r;
    asm("cvt.rna.tf32.f32 %0, %1;" : "=r"(r) : "f"(x));
    return r;
}

__device__ __forceinline__ void mma8(float* c, const unsigned* a, const unsigned* b) {
    asm volatile(
        "mma.sync.aligned.m16n8k8.row.col.f32.tf32.tf32.f32 "
        "{%0,%1,%2,%3}, {%4,%5,%6,%7}, {%8,%9}, {%0,%1,%2,%3};\n"
        : "+f"(c[0]), "+f"(c[1]), "+f"(c[2]), "+f"(c[3])
        : "r"(a[0]), "r"(a[1]), "r"(a[2]), "r"(a[3]), "r"(b[0]), "r"(b[1]));
}

__global__ __launch_bounds__(256, 2)
void k_mma_nt(const float* __restrict__ A, const float* __restrict__ Bw,
              float* __restrict__ C, int M, int N, int K,
              const float* __restrict__ bias, const float* __restrict__ resid,
              int dogelu) {
    __shared__ unsigned As[2][128][20];
    __shared__ unsigned Bs[2][128][20];
    const int bm = blockIdx.y * 128, bn = blockIdx.x * 128;
    const int tid = threadIdx.x;
    const int lane = tid & 31, warp = tid >> 5;
    const int wm = (warp & 1) * 64, wn = (warp >> 1) * 32;
    const int gid = lane >> 2, cid = lane & 3;
    const int lrow = tid >> 1, lcol = (tid & 1) * 8;
    const float* Ag = A  + (size_t)(bm + lrow) * K + lcol;
    const float* Bg = Bw + (size_t)(bn + lrow) * K + lcol;

    float acc[4][4][4];
#pragma unroll
    for (int i = 0; i < 4; i++)
#pragma unroll
        for (int j = 0; j < 4; j++)
#pragma unroll
            for (int r = 0; r < 4; r++) acc[i][j][r] = 0.f;

    // prologue: stage 0
    {
        float4 a0 = *(const float4*)(Ag);
        float4 a1 = *(const float4*)(Ag + 4);
        float4 b0 = *(const float4*)(Bg);
        float4 b1 = *(const float4*)(Bg + 4);
        unsigned* pa = &As[0][lrow][lcol];
        pa[0] = f2tf(a0.x); pa[1] = f2tf(a0.y); pa[2] = f2tf(a0.z); pa[3] = f2tf(a0.w);
        pa[4] = f2tf(a1.x); pa[5] = f2tf(a1.y); pa[6] = f2tf(a1.z); pa[7] = f2tf(a1.w);
        unsigned* pb = &Bs[0][lrow][lcol];
        pb[0] = f2tf(b0.x); pb[1] = f2tf(b0.y); pb[2] = f2tf(b0.z); pb[3] = f2tf(b0.w);
        pb[4] = f2tf(b1.x); pb[5] = f2tf(b1.y); pb[6] = f2tf(b1.z); pb[7] = f2tf(b1.w);
    }
    __syncthreads();

    const int nk = K >> 4;
    for (int kt = 0; kt < nk; kt++) {
        const int s = kt & 1;
        float4 pa0, pa1, pb0, pb1;
        if (kt + 1 < nk) {
            const float* Agn = Ag + (kt + 1) * 16;
            const float* Bgn = Bg + (kt + 1) * 16;
            pa0 = *(const float4*)(Agn);
            pa1 = *(const float4*)(Agn + 4);
            pb0 = *(const float4*)(Bgn);
            pb1 = *(const float4*)(Bgn + 4);
        }
#pragma unroll
        for (int ks = 0; ks < 16; ks += 8) {
            unsigned af[4][4], bf[4][2];
#pragma unroll
            for (int mi = 0; mi < 4; mi++) {
                const unsigned* p = &As[s][wm + mi * 16 + gid][ks + cid];
                af[mi][0] = p[0];
                af[mi][1] = p[8 * 20];
                af[mi][2] = p[4];
                af[mi][3] = p[8 * 20 + 4];
            }
#pragma unroll
            for (int ni = 0; ni < 4; ni++) {
                const unsigned* p = &Bs[s][wn + ni * 8 + gid][ks + cid];
                bf[ni][0] = p[0];
                bf[ni][1] = p[4];
            }
#pragma unroll
            for (int mi = 0; mi < 4; mi++)
#pragma unroll
                for (int ni = 0; ni < 4; ni++)
                    mma8(acc[mi][ni], af[mi], bf[ni]);
        }
        if (kt + 1 < nk) {
            const int sn = s ^ 1;
            unsigned* pa = &As[sn][lrow][lcol];
            pa[0] = f2tf(pa0.x); pa[1] = f2tf(pa0.y); pa[2] = f2tf(pa0.z); pa[3] = f2tf(pa0.w);
            pa[4] = f2tf(pa1.x); pa[5] = f2tf(pa1.y); pa[6] = f2tf(pa1.z); pa[7] = f2tf(pa1.w);
            unsigned* pb = &Bs[sn][lrow][lcol];
            pb[0] = f2tf(pb0.x); pb[1] = f2tf(pb0.y); pb[2] = f2tf(pb0.z); pb[3] = f2tf(pb0.w);
            pb[4] = f2tf(pb1.x); pb[5] = f2tf(pb1.y); pb[6] = f2tf(pb1.z); pb[7] = f2tf(pb1.w);
            __syncthreads();
        }
    }

    // epilogue
#pragma unroll
    for (int mi = 0; mi < 4; mi++) {
        int r0 = bm + wm + mi * 16 + gid;
#pragma unroll
        for (int ni = 0; ni < 4; ni++) {
            int c0 = bn + wn + ni * 8 + 2 * cid;
            float v00 = acc[mi][ni][0], v01 = acc[mi][ni][1];
            float v10 = acc[mi][ni][2], v11 = acc[mi][ni][3];
            if (bias) {
                float b0v = bias[c0], b1v = bias[c0 + 1];
                v00 += b0v; v01 += b1v; v10 += b0v; v11 += b1v;
            }
            if (resid) {
                const float* rr0 = resid + (size_t)r0 * N + c0;
                const float* rr1 = resid + (size_t)(r0 + 8) * N + c0;
                v00 += rr0[0]; v01 += rr0[1]; v10 += rr1[0]; v11 += rr1[1];
            }
            if (dogelu) {
                v00 = 0.5f * v00 * (1.0f + erff(v00 * 0.70710678118654752f));
                v01 = 0.5f * v01 * (1.0f + erff(v01 * 0.70710678118654752f));
                v10 = 0.5f * v10 * (1.0f + erff(v10 * 0.70710678118654752f));
                v11 = 0.5f * v11 * (1.0f + erff(v11 * 0.70710678118654752f));
            }
            *(float2*)&C[(size_t)r0 * N + c0]       = make_float2(v00, v01);
            *(float2*)&C[(size_t)(r0 + 8) * N + c0] = make_float2(v10, v11);
        }
    }
}

// ---------------- attention scores: S = Q K^T * scale + box-mask ------------
__global__ __launch_bounds__(256)
void k_scores(const float* __restrict__ qkv) {
    const int bh = blockIdx.z;
    const int b = bh / H_, h = bh % H_;
    const int i0 = blockIdx.y * 64, j0 = blockIdx.x * 64;
    const int t = threadIdx.x;
    const int tm = (t >> 4) * 4, tn = (t & 15) * 4;
    const size_t sbase = ((size_t)bh * L_ + i0) * L_ + j0;

    if (j0 > i0 + 63) { // fully above the diagonal: all masked
#pragma unroll
        for (int i = 0; i < 4; i++)
#pragma unroll
            for (int j = 0; j < 4; j++)
                g_sc[sbase + (size_t)(tm + i) * L_ + tn + j] = -1e30f;
        return;
    }

    __shared__ float Qs[64][65];
    __shared__ float Ks[64][65];
    const float* qb = qkv + (size_t)(b * L_ + i0) * (3 * D_) + h * HD_;
    const float* kb = qkv + (size_t)(b * L_ + j0) * (3 * D_) + D_ + h * HD_;
    for (int idx = t; idx < 64 * 64; idx += 256) {
        int r = idx >> 6, c = idx & 63;
        Qs[r][c] = qb[(size_t)r * (3 * D_) + c];
        Ks[r][c] = kb[(size_t)r * (3 * D_) + c];
    }
    __syncthreads();

    float acc[4][4] = {};
#pragma unroll 8
    for (int d = 0; d < 64; d++) {
        float q[4], k[4];
#pragma unroll
        for (int i = 0; i < 4; i++) { q[i] = Qs[tm + i][d]; k[i] = Ks[tn + i][d]; }
#pragma unroll
        for (int i = 0; i < 4; i++)
#pragma unroll
            for (int j = 0; j < 4; j++) acc[i][j] += q[i] * k[j];
    }

    const int* segb = g_seg + b * L_;
    const int* gkb  = g_gkey + b * L_;
    const int* vab  = g_valid + b * L_;
#pragma unroll
    for (int i = 0; i < 4; i++) {
        int gi = i0 + tm + i;
        int si = segb[gi];
#pragma unroll
        for (int j = 0; j < 4; j++) {
            int gj = j0 + tn + j;
            float v = acc[i][j] * 0.125f; // 1/sqrt(64)
            bool allowed = (gj <= gi) && vab[gj] &&
                           (segb[gj] == si || gkb[gj] || (gi - gj) <= WIN_);
            g_sc[sbase + (size_t)(tm + i) * L_ + tn + j] = allowed ? v : -1e30f;
        }
    }
}

// ---------------- row softmax over L=1024 -----------------------------------
__global__ __launch_bounds__(256)
void k_softmax() {
    size_t row = blockIdx.x;
    float* p = g_sc + row * L_;
    int t = threadIdx.x;
    float v[4];
    float mx = -1e30f;
#pragma unroll
    for (int i = 0; i < 4; i++) { v[i] = p[i * 256 + t]; mx = fmaxf(mx, v[i]); }
    __shared__ float rmax[8], rsum[8];
#pragma unroll
    for (int o = 16; o > 0; o >>= 1) mx = fmaxf(mx, __shfl_xor_sync(0xffffffffu, mx, o));
    if ((t & 31) == 0) rmax[t >> 5] = mx;
    __syncthreads();
    if (t < 32) {
        float m = (t < 8) ? rmax[t] : -1e30f;
#pragma unroll
        for (int o = 4; o > 0; o >>= 1) m = fmaxf(m, __shfl_xor_sync(0xffffffffu, m, o));
        if (t == 0) rmax[0] = m;
    }
    __syncthreads();
    float bm = rmax[0];
    float s = 0.f;
#pragma unroll
    for (int i = 0; i < 4; i++) { v[i] = __expf(v[i] - bm); s += v[i]; }
#pragma unroll
    for (int o = 16; o > 0; o >>= 1) s += __shfl_xor_sync(0xffffffffu, s, o);
    if ((t & 31) == 0) rsum[t >> 5] = s;
    __syncthreads();
    if (t < 32) {
        float a = (t < 8) ? rsum[t] : 0.f;
#pragma unroll
        for (int o = 4; o > 0; o >>= 1) a += __shfl_xor_sync(0xffffffffu, a, o);
        if (t == 0) rsum[0] = a;
    }
    __syncthreads();
    float inv = 1.0f / rsum[0];
#pragma unroll
    for (int i = 0; i < 4; i++) p[i * 256 + t] = v[i] * inv;
}

// ---------------- y = P @ V --------------------------------------------------
__global__ __launch_bounds__(256)
void k_av(const float* __restrict__ qkv) {
    const int bh = blockIdx.y;
    const int b = bh / H_, h = bh % H_;
    const int i0 = blockIdx.x * 64;
    const int t = threadIdx.x;
    const int tm = (t >> 4) * 4, tn = (t & 15) * 4;
    __shared__ float Ps[64][65];
    __shared__ float Vs[64][65];
    float acc[4][4] = {};
    const float* vb = qkv + (size_t)b * L_ * 3 * D_ + 2 * D_ + h * HD_;
    for (int j0 = 0; j0 <= i0 + 63; j0 += 64) {
        for (int idx = t; idx < 64 * 64; idx += 256) {
            int r = idx >> 6, c = idx & 63;
            Ps[r][c] = g_sc[((size_t)bh * L_ + i0 + r) * L_ + j0 + c];
            Vs[r][c] = vb[(size_t)(j0 + r) * 3 * D_ + c];
        }
        __syncthreads();
#pragma unroll 4
        for (int jj = 0; jj < 64; jj++) {
            float pr[4], vv[4];
#pragma unroll
            for (int i = 0; i < 4; i++) { pr[i] = Ps[tm + i][jj]; vv[i] = Vs[jj][tn + i]; }
#pragma unroll
            for (int i = 0; i < 4; i++)
#pragma unroll
                for (int j = 0; j < 4; j++) acc[i][j] += pr[i] * vv[j];
        }
        __syncthreads();
    }
    float* yb = g_y + (size_t)(b * L_ + i0) * D_ + h * HD_;
#pragma unroll
    for (int i = 0; i < 4; i++)
#pragma unroll
        for (int j = 0; j < 4; j++)
            yb[(size_t)(tm + i) * D_ + tn + j] = acc[i][j];
}

// ---------------- host side --------------------------------------------------
static void gemm(const float* A, const float* Bw, float* C, int M, int N, int K,
                 const float* bias, const float* resid, bool gelu_flag) {
    dim3 grid(N / 128, M / 128);
    k_mma_nt<<<grid, 256>>>(A, Bw, C, M, N, K, bias, resid, gelu_flag ? 1 : 0);
}

extern "C" void kernel_launch(void* const* d_in, const int* in_sizes, int n_in,
                              void* d_out, int out_size) {
    const int*   tokens    = (const int*)d_in[0];
    const int*   types     = (const int*)d_in[1];
    const int*   attn_mask = (const int*)d_in[2];
    const float* tok_emb   = (const float*)d_in[3];
    const float* type_emb  = (const float*)d_in[4];
    const float* pos_emb   = (const float*)d_in[5];
    const float* qkv_w     = (const float*)d_in[6];
    const float* out_w     = (const float*)d_in[7];
    const float* ln1_s     = (const float*)d_in[8];
    const float* ln1_b     = (const float*)d_in[9];
    const float* ln2_s     = (const float*)d_in[10];
    const float* ln2_b     = (const float*)d_in[11];
    const float* ff_w1     = (const float*)d_in[12];
    const float* ff_b1     = (const float*)d_in[13];
    const float* ff_w2     = (const float*)d_in[14];
    const float* ff_b2     = (const float*)d_in[15];
    const float* lnf_s     = (const float*)d_in[16];
    const float* lnf_b     = (const float*)d_in[17];
    const float* head_w    = (const float*)d_in[18];
    float* out = (float*)d_out;

    float *x, *h, *qkv, *y, *ff;
    cudaGetSymbolAddress((void**)&x, g_x);
    cudaGetSymbolAddress((void**)&h, g_h);
    cudaGetSymbolAddress((void**)&qkv, g_qkv);
    cudaGetSymbolAddress((void**)&y, g_y);
    cudaGetSymbolAddress((void**)&ff, g_ff);

    k_embed<<<(M_ * D_ + 255) / 256, 256>>>(tokens, types, tok_emb, type_emb, pos_emb);
    k_maskprep<<<1, 32>>>(tokens, attn_mask);

    for (int l = 0; l < NL_; l++) {
        k_ln<<<M_, 256>>>(x, ln1_s + l * D_, ln1_b + l * D_, h);
        gemm(h, qkv_w + (size_t)l * 3 * D_ * D_, qkv, M_, 3 * D_, D_, nullptr, nullptr, false);
        k_scores<<<dim3(L_ / 64, L_ / 64, B_ * H_), 256>>>(qkv);
        k_softmax<<<B_ * H_ * L_, 256>>>();
        k_av<<<dim3(L_ / 64, B_ * H_), 256>>>(qkv);
        gemm(y, out_w + (size_t)l * D_ * D_, x, M_, D_, D_, nullptr, x, false);
        k_ln<<<M_, 256>>>(x, ln2_s + l * D_, ln2_b + l * D_, h);
        gemm(h, ff_w1 + (size_t)l * FF_ * D_, ff, M_, FF_, D_, ff_b1 + l * FF_, nullptr, true);
        gemm(ff, ff_w2 + (size_t)l * D_ * FF_, x, M_, D_, FF_, ff_b2 + l * D_, x, false);
    }
    k_ln<<<M_, 256>>>(x, lnf_s, lnf_b, h);
    gemm(h, head_w, out, M_, V_, D_, nullptr, nullptr, false);
}